// round 4
// baseline (speedup 1.0000x reference)
#include <cuda_runtime.h>
#include <cuda_bf16.h>
#include <cstdint>

#define N_NODES 10000
#define N_EDGES 640000
#define D_FEAT  128

// CSR scratch (device globals: no allocation allowed in kernel_launch)
__device__ int g_cnt[N_NODES];
__device__ int g_off[N_NODES + 1];
__device__ int g_cur[N_NODES];
__device__ int g_eid[N_EDGES];

// ---------------------------------------------------------------------------
// 1. zero degree counts
// ---------------------------------------------------------------------------
__global__ void zero_cnt_kernel() {
    int i = blockIdx.x * blockDim.x + threadIdx.x;
    if (i < N_NODES) g_cnt[i] = 0;
}

// ---------------------------------------------------------------------------
// 2. histogram of receiver indices (int atomics: cheap, spread addresses)
// ---------------------------------------------------------------------------
__global__ void hist_kernel(const int* __restrict__ recv_idx) {
    int e = blockIdx.x * blockDim.x + threadIdx.x;
    if (e < N_EDGES) atomicAdd(&g_cnt[recv_idx[e]], 1);
}

// ---------------------------------------------------------------------------
// 3. exclusive scan over counts -> offsets + fill cursors (single block)
// ---------------------------------------------------------------------------
#define SCAN_T 1024
#define SCAN_PER 10   // 1024*10 = 10240 >= 10000
__global__ __launch_bounds__(SCAN_T) void scan_kernel() {
    __shared__ int warp_sums[32];
    int tid  = threadIdx.x;
    int lane = tid & 31;
    int wid  = tid >> 5;
    int base = tid * SCAN_PER;

    int local[SCAN_PER];
    int s = 0;
    #pragma unroll
    for (int i = 0; i < SCAN_PER; i++) {
        int idx = base + i;
        int c = (idx < N_NODES) ? g_cnt[idx] : 0;
        local[i] = s;       // exclusive within chunk
        s += c;
    }
    // inclusive scan of chunk sums across warp
    int v = s;
    #pragma unroll
    for (int d = 1; d < 32; d <<= 1) {
        int n = __shfl_up_sync(0xFFFFFFFFu, v, d);
        if (lane >= d) v += n;
    }
    if (lane == 31) warp_sums[wid] = v;
    __syncthreads();
    if (wid == 0) {
        int w = warp_sums[lane];
        #pragma unroll
        for (int d = 1; d < 32; d <<= 1) {
            int n = __shfl_up_sync(0xFFFFFFFFu, w, d);
            if (lane >= d) w += n;
        }
        warp_sums[lane] = w;   // inclusive across warps
    }
    __syncthreads();
    int warp_excl   = (wid == 0) ? 0 : warp_sums[wid - 1];
    int thread_excl = warp_excl + (v - s);

    #pragma unroll
    for (int i = 0; i < SCAN_PER; i++) {
        int idx = base + i;
        if (idx < N_NODES) {
            int off = thread_excl + local[i];
            g_off[idx] = off;
            g_cur[idx] = off;
        }
    }
    if (tid == 0) g_off[N_NODES] = N_EDGES;
}

// ---------------------------------------------------------------------------
// 4. fill CSR edge-id list
// ---------------------------------------------------------------------------
__global__ void fill_kernel(const int* __restrict__ recv_idx) {
    int e = blockIdx.x * blockDim.x + threadIdx.x;
    if (e < N_EDGES) {
        int node = recv_idx[e];
        int pos = atomicAdd(&g_cur[node], 1);
        g_eid[pos] = e;
    }
}

// ---------------------------------------------------------------------------
// 5. fused gather (segment-sum) + [node_feat | agg] @ W + b
// Block: 512 threads, 64-node tile.
//   Phase A: each warp gathers 4 nodes' edge rows into AggS (smem, 32KB).
//            Lane l accumulates feature floats [4l, 4l+4) as a float4.
//   Phase B: tiled GEMM. K chunked by 16. First half reads node_feat (staged
//            into Xs), second half reads AggS directly. W chunk staged in Ws.
//   Thread (wid, lane): 4 nodes (wid*4..+3) x 4 cols (lane*4..+3).
// ---------------------------------------------------------------------------
#define NT 64
#define KC 16

__global__ __launch_bounds__(512) void fused_kernel(
    const float* __restrict__ edge_feat,
    const float* __restrict__ node_feat,
    const float* __restrict__ W,
    const float* __restrict__ b,
    float* __restrict__ out)
{
    __shared__ float AggS[NT * D_FEAT];   // 32 KB
    __shared__ float Ws[KC * D_FEAT];     //  8 KB
    __shared__ float Xs[NT * KC];         //  4 KB

    const int tid  = threadIdx.x;
    const int lane = tid & 31;
    const int wid  = tid >> 5;            // 0..15
    const int n0   = blockIdx.x * NT;

    // ---------------- Phase A: gather ----------------
    #pragma unroll
    for (int j = 0; j < 4; j++) {
        int n  = wid * 4 + j;
        int gn = n0 + n;
        float4 acc = make_float4(0.f, 0.f, 0.f, 0.f);
        if (gn < N_NODES) {
            int beg = g_off[gn];
            int end = g_off[gn + 1];
            int t = beg;
            for (; t + 8 <= end; t += 8) {
                int e[8];
                #pragma unroll
                for (int u = 0; u < 8; u++) e[u] = g_eid[t + u];
                float4 v[8];
                #pragma unroll
                for (int u = 0; u < 8; u++)
                    v[u] = *reinterpret_cast<const float4*>(
                        edge_feat + (size_t)e[u] * D_FEAT + lane * 4);
                #pragma unroll
                for (int u = 0; u < 8; u++) {
                    acc.x += v[u].x; acc.y += v[u].y;
                    acc.z += v[u].z; acc.w += v[u].w;
                }
            }
            for (; t < end; t++) {
                int e = g_eid[t];
                float4 v = *reinterpret_cast<const float4*>(
                    edge_feat + (size_t)e * D_FEAT + lane * 4);
                acc.x += v.x; acc.y += v.y; acc.z += v.z; acc.w += v.w;
            }
        }
        *reinterpret_cast<float4*>(&AggS[n * D_FEAT + lane * 4]) = acc;
    }
    __syncthreads();

    // ---------------- Phase B: GEMM ----------------
    float acc[4][4];
    #pragma unroll
    for (int i = 0; i < 4; i++)
        #pragma unroll
        for (int jj = 0; jj < 4; jj++) acc[i][jj] = 0.f;

    // First half: K in [0,128) from node_feat
    for (int k0 = 0; k0 < D_FEAT; k0 += KC) {
        {   // stage W[k0 : k0+KC, :]  (512 float4 / 512 threads)
            const float4* src = reinterpret_cast<const float4*>(W + k0 * D_FEAT);
            reinterpret_cast<float4*>(Ws)[tid] = src[tid];
        }
        #pragma unroll
        for (int i = tid; i < NT * KC; i += 512) {
            int n = i >> 4;           // / KC
            int k = i & (KC - 1);
            int gn = n0 + n;
            Xs[i] = (gn < N_NODES) ? node_feat[(size_t)gn * D_FEAT + k0 + k] : 0.f;
        }
        __syncthreads();
        #pragma unroll
        for (int kk = 0; kk < KC; kk++) {
            float4 w = *reinterpret_cast<const float4*>(&Ws[kk * D_FEAT + lane * 4]);
            #pragma unroll
            for (int n = 0; n < 4; n++) {
                float x = Xs[(wid * 4 + n) * KC + kk];
                acc[n][0] = fmaf(x, w.x, acc[n][0]);
                acc[n][1] = fmaf(x, w.y, acc[n][1]);
                acc[n][2] = fmaf(x, w.z, acc[n][2]);
                acc[n][3] = fmaf(x, w.w, acc[n][3]);
            }
        }
        __syncthreads();
    }

    // Second half: K in [128,256) from AggS (already in smem)
    for (int k0 = 0; k0 < D_FEAT; k0 += KC) {
        {
            const float4* src = reinterpret_cast<const float4*>(W + (D_FEAT + k0) * D_FEAT);
            reinterpret_cast<float4*>(Ws)[tid] = src[tid];
        }
        __syncthreads();
        #pragma unroll
        for (int kk = 0; kk < KC; kk++) {
            float4 w = *reinterpret_cast<const float4*>(&Ws[kk * D_FEAT + lane * 4]);
            #pragma unroll
            for (int n = 0; n < 4; n++) {
                float x = AggS[(wid * 4 + n) * D_FEAT + k0 + kk];
                acc[n][0] = fmaf(x, w.x, acc[n][0]);
                acc[n][1] = fmaf(x, w.y, acc[n][1]);
                acc[n][2] = fmaf(x, w.z, acc[n][2]);
                acc[n][3] = fmaf(x, w.w, acc[n][3]);
            }
        }
        __syncthreads();
    }

    // Epilogue
    float4 bb = *reinterpret_cast<const float4*>(&b[lane * 4]);
    #pragma unroll
    for (int n = 0; n < 4; n++) {
        int gn = n0 + wid * 4 + n;
        if (gn < N_NODES) {
            float4 r;
            r.x = acc[n][0] + bb.x;
            r.y = acc[n][1] + bb.y;
            r.z = acc[n][2] + bb.z;
            r.w = acc[n][3] + bb.w;
            *reinterpret_cast<float4*>(out + (size_t)gn * D_FEAT + lane * 4) = r;
        }
    }
}

// ---------------------------------------------------------------------------
extern "C" void kernel_launch(void* const* d_in, const int* in_sizes, int n_in,
                              void* d_out, int out_size) {
    const float* edge_feat = (const float*)d_in[0];
    const float* node_feat = (const float*)d_in[1];
    const int*   recv_idx  = (const int*)d_in[2];
    const float* W         = (const float*)d_in[3];
    const float* b         = (const float*)d_in[4];
    float*       out       = (float*)d_out;

    zero_cnt_kernel<<<(N_NODES + 1023) / 1024, 1024>>>();
    hist_kernel<<<(N_EDGES + 255) / 256, 256>>>(recv_idx);
    scan_kernel<<<1, SCAN_T>>>();
    fill_kernel<<<(N_EDGES + 255) / 256, 256>>>(recv_idx);

    int blocks = (N_NODES + NT - 1) / NT;   // 157
    fused_kernel<<<blocks, 512>>>(edge_feat, node_feat, W, b, out);
}

// round 5
// speedup vs baseline: 1.0550x; 1.0550x over previous
#include <cuda_runtime.h>
#include <cuda_bf16.h>
#include <cstdint>

#define N_NODES 10000
#define N_EDGES 640000
#define D_FEAT  128

// CSR scratch (device globals: no allocation allowed in kernel_launch)
__device__ int g_cnt[N_NODES];
__device__ int g_off[N_NODES + 1];
__device__ int g_cur[N_NODES];
__device__ int g_eid[N_EDGES];

// ---------------------------------------------------------------------------
// 1. zero degree counts
// ---------------------------------------------------------------------------
__global__ void zero_cnt_kernel() {
    int i = blockIdx.x * blockDim.x + threadIdx.x;
    if (i < N_NODES) g_cnt[i] = 0;
}

// ---------------------------------------------------------------------------
// 2. histogram of receiver indices. ILP-4: int4 load, 4 independent REDs
//    (no return value used -> compiles to REDG, no round-trip latency).
// ---------------------------------------------------------------------------
__global__ void hist_kernel(const int* __restrict__ recv_idx) {
    int i = blockIdx.x * blockDim.x + threadIdx.x;   // quad index
    if (i < N_EDGES / 4) {
        int4 r = reinterpret_cast<const int4*>(recv_idx)[i];
        atomicAdd(&g_cnt[r.x], 1);
        atomicAdd(&g_cnt[r.y], 1);
        atomicAdd(&g_cnt[r.z], 1);
        atomicAdd(&g_cnt[r.w], 1);
    }
}

// ---------------------------------------------------------------------------
// 3. exclusive scan over counts -> offsets + fill cursors (single block)
// ---------------------------------------------------------------------------
#define SCAN_T 1024
#define SCAN_PER 10   // 1024*10 = 10240 >= 10000
__global__ __launch_bounds__(SCAN_T) void scan_kernel() {
    __shared__ int warp_sums[32];
    int tid  = threadIdx.x;
    int lane = tid & 31;
    int wid  = tid >> 5;
    int base = tid * SCAN_PER;

    int local[SCAN_PER];
    int s = 0;
    #pragma unroll
    for (int i = 0; i < SCAN_PER; i++) {
        int idx = base + i;
        int c = (idx < N_NODES) ? g_cnt[idx] : 0;
        local[i] = s;       // exclusive within chunk
        s += c;
    }
    int v = s;
    #pragma unroll
    for (int d = 1; d < 32; d <<= 1) {
        int n = __shfl_up_sync(0xFFFFFFFFu, v, d);
        if (lane >= d) v += n;
    }
    if (lane == 31) warp_sums[wid] = v;
    __syncthreads();
    if (wid == 0) {
        int w = warp_sums[lane];
        #pragma unroll
        for (int d = 1; d < 32; d <<= 1) {
            int n = __shfl_up_sync(0xFFFFFFFFu, w, d);
            if (lane >= d) w += n;
        }
        warp_sums[lane] = w;
    }
    __syncthreads();
    int warp_excl   = (wid == 0) ? 0 : warp_sums[wid - 1];
    int thread_excl = warp_excl + (v - s);

    #pragma unroll
    for (int i = 0; i < SCAN_PER; i++) {
        int idx = base + i;
        if (idx < N_NODES) {
            int off = thread_excl + local[i];
            g_off[idx] = off;
            g_cur[idx] = off;
        }
    }
    if (tid == 0) g_off[N_NODES] = N_EDGES;
}

// ---------------------------------------------------------------------------
// 4. fill CSR edge-id list. ILP-4: 4 independent atomicAdd chains per thread
//    so ATOMG return latency (~318cyc) overlaps 4-deep.
// ---------------------------------------------------------------------------
__global__ void fill_kernel(const int* __restrict__ recv_idx) {
    int i = blockIdx.x * blockDim.x + threadIdx.x;   // quad index
    if (i < N_EDGES / 4) {
        int4 r = reinterpret_cast<const int4*>(recv_idx)[i];
        int e0 = i * 4;
        int p0 = atomicAdd(&g_cur[r.x], 1);
        int p1 = atomicAdd(&g_cur[r.y], 1);
        int p2 = atomicAdd(&g_cur[r.z], 1);
        int p3 = atomicAdd(&g_cur[r.w], 1);
        g_eid[p0] = e0;
        g_eid[p1] = e0 + 1;
        g_eid[p2] = e0 + 2;
        g_eid[p3] = e0 + 3;
    }
}

// ---------------------------------------------------------------------------
// 5. fused gather (segment-sum) + [node_feat | agg] @ W + b
// Block: 256 threads, 32-node tile -> 313 blocks (~2/SM) so one block's
// DRAM-bound gather overlaps another's FMA-bound GEMM on the same SM.
//   Phase A: warp w gathers nodes w*4..w*4+3; lane l owns feature float4 l.
//   Phase B: tiled GEMM, K chunks of 16; first half node_feat via Xs,
//            second half straight from AggS. Thread (wid,lane):
//            4 nodes x 4 cols register tile.
// ---------------------------------------------------------------------------
#define NT 32
#define KC 16

__global__ __launch_bounds__(256) void fused_kernel(
    const float* __restrict__ edge_feat,
    const float* __restrict__ node_feat,
    const float* __restrict__ W,
    const float* __restrict__ b,
    float* __restrict__ out)
{
    __shared__ float AggS[NT * D_FEAT];   // 16 KB
    __shared__ float Ws[KC * D_FEAT];     //  8 KB
    __shared__ float Xs[NT * KC];         //  2 KB

    const int tid  = threadIdx.x;
    const int lane = tid & 31;
    const int wid  = tid >> 5;            // 0..7
    const int n0   = blockIdx.x * NT;

    // ---------------- Phase A: gather ----------------
    #pragma unroll
    for (int j = 0; j < 4; j++) {
        int n  = wid * 4 + j;
        int gn = n0 + n;
        float4 acc = make_float4(0.f, 0.f, 0.f, 0.f);
        if (gn < N_NODES) {
            int beg = g_off[gn];
            int end = g_off[gn + 1];
            int t = beg;
            for (; t + 8 <= end; t += 8) {
                int e[8];
                #pragma unroll
                for (int u = 0; u < 8; u++) e[u] = g_eid[t + u];
                float4 v[8];
                #pragma unroll
                for (int u = 0; u < 8; u++)
                    v[u] = *reinterpret_cast<const float4*>(
                        edge_feat + (size_t)e[u] * D_FEAT + lane * 4);
                #pragma unroll
                for (int u = 0; u < 8; u++) {
                    acc.x += v[u].x; acc.y += v[u].y;
                    acc.z += v[u].z; acc.w += v[u].w;
                }
            }
            for (; t < end; t++) {
                int e = g_eid[t];
                float4 v = *reinterpret_cast<const float4*>(
                    edge_feat + (size_t)e * D_FEAT + lane * 4);
                acc.x += v.x; acc.y += v.y; acc.z += v.z; acc.w += v.w;
            }
        }
        *reinterpret_cast<float4*>(&AggS[n * D_FEAT + lane * 4]) = acc;
    }
    __syncthreads();

    // ---------------- Phase B: GEMM ----------------
    float acc[4][4];
    #pragma unroll
    for (int i = 0; i < 4; i++)
        #pragma unroll
        for (int jj = 0; jj < 4; jj++) acc[i][jj] = 0.f;

    // First half: K in [0,128) from node_feat
    for (int k0 = 0; k0 < D_FEAT; k0 += KC) {
        {   // stage W[k0 : k0+KC, :]  (512 float4 / 256 threads)
            const float4* src = reinterpret_cast<const float4*>(W + k0 * D_FEAT);
            float4* dst = reinterpret_cast<float4*>(Ws);
            dst[tid]       = src[tid];
            dst[tid + 256] = src[tid + 256];
        }
        #pragma unroll
        for (int i = tid; i < NT * KC; i += 256) {
            int n = i >> 4;           // / KC
            int k = i & (KC - 1);
            int gn = n0 + n;
            Xs[i] = (gn < N_NODES) ? node_feat[(size_t)gn * D_FEAT + k0 + k] : 0.f;
        }
        __syncthreads();
        #pragma unroll
        for (int kk = 0; kk < KC; kk++) {
            float4 w = *reinterpret_cast<const float4*>(&Ws[kk * D_FEAT + lane * 4]);
            #pragma unroll
            for (int n = 0; n < 4; n++) {
                float x = Xs[(wid * 4 + n) * KC + kk];
                acc[n][0] = fmaf(x, w.x, acc[n][0]);
                acc[n][1] = fmaf(x, w.y, acc[n][1]);
                acc[n][2] = fmaf(x, w.z, acc[n][2]);
                acc[n][3] = fmaf(x, w.w, acc[n][3]);
            }
        }
        __syncthreads();
    }

    // Second half: K in [128,256) from AggS (already in smem)
    for (int k0 = 0; k0 < D_FEAT; k0 += KC) {
        {
            const float4* src = reinterpret_cast<const float4*>(W + (D_FEAT + k0) * D_FEAT);
            float4* dst = reinterpret_cast<float4*>(Ws);
            dst[tid]       = src[tid];
            dst[tid + 256] = src[tid + 256];
        }
        __syncthreads();
        #pragma unroll
        for (int kk = 0; kk < KC; kk++) {
            float4 w = *reinterpret_cast<const float4*>(&Ws[kk * D_FEAT + lane * 4]);
            #pragma unroll
            for (int n = 0; n < 4; n++) {
                float x = AggS[(wid * 4 + n) * D_FEAT + k0 + kk];
                acc[n][0] = fmaf(x, w.x, acc[n][0]);
                acc[n][1] = fmaf(x, w.y, acc[n][1]);
                acc[n][2] = fmaf(x, w.z, acc[n][2]);
                acc[n][3] = fmaf(x, w.w, acc[n][3]);
            }
        }
        __syncthreads();
    }

    // Epilogue
    float4 bb = *reinterpret_cast<const float4*>(&b[lane * 4]);
    #pragma unroll
    for (int n = 0; n < 4; n++) {
        int gn = n0 + wid * 4 + n;
        if (gn < N_NODES) {
            float4 r;
            r.x = acc[n][0] + bb.x;
            r.y = acc[n][1] + bb.y;
            r.z = acc[n][2] + bb.z;
            r.w = acc[n][3] + bb.w;
            *reinterpret_cast<float4*>(out + (size_t)gn * D_FEAT + lane * 4) = r;
        }
    }
}

// ---------------------------------------------------------------------------
extern "C" void kernel_launch(void* const* d_in, const int* in_sizes, int n_in,
                              void* d_out, int out_size) {
    const float* edge_feat = (const float*)d_in[0];
    const float* node_feat = (const float*)d_in[1];
    const int*   recv_idx  = (const int*)d_in[2];
    const float* W         = (const float*)d_in[3];
    const float* b         = (const float*)d_in[4];
    float*       out       = (float*)d_out;

    zero_cnt_kernel<<<(N_NODES + 1023) / 1024, 1024>>>();
    hist_kernel<<<(N_EDGES / 4 + 255) / 256, 256>>>(recv_idx);
    scan_kernel<<<1, SCAN_T>>>();
    fill_kernel<<<(N_EDGES / 4 + 255) / 256, 256>>>(recv_idx);

    int blocks = (N_NODES + NT - 1) / NT;   // 313
    fused_kernel<<<blocks, 256>>>(edge_feat, node_feat, W, b, out);
}